// round 5
// baseline (speedup 1.0000x reference)
#include <cuda_runtime.h>
#include <cuda_bf16.h>

namespace {

constexpr int B  = 256;
constexpr int L  = 128;
constexpr int H  = 512;
constexpr int H4 = 2048;

typedef unsigned long long ull;

// ---------------- device state (allocation-free scratch; all GEMM operands k-major) ----------
__device__ float g_hT[2][H][B];                     // hidden transposed, double buffered
__device__ float g_cT[H][B];                        // cell transposed
__device__ float g_ctxT[H][B];                      // attention context transposed
__device__ float g_enc_outT[H][L * B];              // fp32, col = t*B + b (encw1 A input)
__device__ __nv_bfloat16 g_enc_outh[(size_t)B * L * H];  // [b][l][h] (attn context)
__device__ __nv_bfloat16 g_enc_w1h[(size_t)L * B * H];   // row = l*B + b (attn scores)
__device__ float g_dec_in[2][B];                    // decoder scalar input
__device__ float g_ewT[H][H4];                      // enc Wh, k-major, gate-interleaved n'=4h+g
__device__ float g_eb4[H4];                         // enc bias, interleaved
__device__ float g_ewi4[H4];                        // enc Wi (scalar input), interleaved
__device__ float g_dwT[2 * H][H4];                  // dec [Wi_main ; Wh], k-major, interleaved
__device__ float g_db4[H4];
__device__ float g_dwi4[H4];                        // dec Wi last column, interleaved
__device__ float g_w1T[H][H];                       // w1, k-major
__device__ float g_w2T[H][H];                       // w2, k-major
__device__ float g_qpart[4][B][H];                  // split-K partials for q

// ---------------- math helpers ----------------
__device__ __forceinline__ float sigmoid_acc(float x) {
    return 1.0f / (1.0f + __expf(-x));
}
__device__ __forceinline__ float tanh_acc(float x) {
    float e = __expf(-2.0f * fabsf(x));
    float r = (1.0f - e) / (1.0f + e);
    return copysignf(r, x);
}
__device__ __forceinline__ float tanh_fast(float x) {
    float y;
    asm("tanh.approx.f32 %0, %1;" : "=f"(y) : "f"(x));
    return y;
}
__device__ __forceinline__ void ffma2(ull& d, ull a, ull b) {
    asm("fma.rn.f32x2 %0, %1, %2, %0;" : "+l"(d) : "l"(a), "l"(b));
}
__device__ __forceinline__ ull pk2(float x, float y) {
    ull r;
    asm("mov.b64 %0, {%1, %2};" : "=l"(r) : "f"(x), "f"(y));
    return r;
}
__device__ __forceinline__ float2 f2bits(ull v) {
    return *reinterpret_cast<float2*>(&v);
}

// ======================================================================================
// smem-free GEMM core: tile 64n x 64m, 256 threads, micro 4n x 4m, FFMA2.
// W is k-major [k][N] (row stride WS), A is k-major [k][M] (row stride AS).
// Per thread per k: 1 LDG.128 (b, warp-broadcast -> L1 hit), 1 LDG.128 (a),
// 6 pack-MOVs, 8 FFMA2. No shared memory, no synchronization.
// ======================================================================================
__device__ __forceinline__ void micro4(const float4 a[4], const float4 b[4], ull acc[4][2]) {
#pragma unroll
    for (int u = 0; u < 4; u++) {
        ull bp0 = pk2(b[u].x, b[u].y);
        ull bp1 = pk2(b[u].z, b[u].w);
        ull ad;
        ad = pk2(a[u].x, a[u].x); ffma2(acc[0][0], ad, bp0); ffma2(acc[0][1], ad, bp1);
        ad = pk2(a[u].y, a[u].y); ffma2(acc[1][0], ad, bp0); ffma2(acc[1][1], ad, bp1);
        ad = pk2(a[u].z, a[u].z); ffma2(acc[2][0], ad, bp0); ffma2(acc[2][1], ad, bp1);
        ad = pk2(a[u].w, a[u].w); ffma2(acc[3][0], ad, bp0); ffma2(acc[3][1], ad, bp1);
    }
}

template <int WS, int AS>
__device__ __forceinline__ void gemm_block(const float* __restrict__ pW,
                                           const float* __restrict__ pA,
                                           int kcount, ull acc[4][2]) {
    // kcount must be a multiple of 8.
    float4 a0[4], b0[4], a1[4], b1[4];
#pragma unroll
    for (int u = 0; u < 4; u++) {
        a0[u] = *(const float4*)(pA + (size_t)u * AS);
        b0[u] = *(const float4*)(pW + (size_t)u * WS);
    }
    pA += (size_t)4 * AS;
    pW += (size_t)4 * WS;
    for (int kb = 0; kb < kcount; kb += 8) {
#pragma unroll
        for (int u = 0; u < 4; u++) {
            a1[u] = *(const float4*)(pA + (size_t)u * AS);
            b1[u] = *(const float4*)(pW + (size_t)u * WS);
        }
        pA += (size_t)4 * AS;
        pW += (size_t)4 * WS;
        micro4(a0, b0, acc);
        if (kb + 8 < kcount) {
#pragma unroll
            for (int u = 0; u < 4; u++) {
                a0[u] = *(const float4*)(pA + (size_t)u * AS);
                b0[u] = *(const float4*)(pW + (size_t)u * WS);
            }
        }
        pA += (size_t)4 * AS;
        pW += (size_t)4 * WS;
        micro4(a1, b1, acc);
    }
}

// ---------------- init ----------------
__global__ void k_init() {
    int i = blockIdx.x * blockDim.x + threadIdx.x;
    int stride = gridDim.x * blockDim.x;
    float* h0 = &g_hT[0][0][0];
    float* c0 = &g_cT[0][0];
    for (int j = i; j < H * B; j += stride) {
        h0[j] = 0.0f;
        c0[j] = 0.0f;
    }
    if (i < B) g_dec_in[0][i] = 0.0f;
}

// ---------------- one-time repacks (k-major, gate-interleaved n' = 4h+g) ----------------
__global__ void k_repack_enc(const float* __restrict__ ewh,
                             const float* __restrict__ eb,
                             const float* __restrict__ ewi) {
    int i = blockIdx.x * blockDim.x + threadIdx.x;
    int stride = gridDim.x * blockDim.x;
    for (int j = i; j < H * H4; j += stride) {
        int k  = j >> 11;            // / 2048
        int np = j & (H4 - 1);
        int hh = np >> 2, g = np & 3;
        g_ewT[k][np] = ewh[(g * H + hh) * H + k];
    }
    if (i < H4) {
        int hh = i >> 2, g = i & 3;
        g_eb4[i]  = eb[g * H + hh];
        g_ewi4[i] = ewi[g * H + hh];
    }
}

__global__ void k_repack_dec(const float* __restrict__ dwi,
                             const float* __restrict__ dwh,
                             const float* __restrict__ db) {
    int i = blockIdx.x * blockDim.x + threadIdx.x;
    int stride = gridDim.x * blockDim.x;
    for (int j = i; j < 2 * H * H4; j += stride) {
        int k  = j >> 11;
        int np = j & (H4 - 1);
        int hh = np >> 2, g = np & 3;
        int row = g * H + hh;
        g_dwT[k][np] = (k < H) ? dwi[row * (H + 1) + k]
                               : dwh[row * H + (k - H)];
    }
    if (i < H4) {
        int hh = i >> 2, g = i & 3;
        g_db4[i]  = db[g * H + hh];
        g_dwi4[i] = dwi[(g * H + hh) * (H + 1) + H];
    }
}

__global__ void k_repack_w(const float* __restrict__ w1, const float* __restrict__ w2) {
    int i = blockIdx.x * blockDim.x + threadIdx.x;
    int stride = gridDim.x * blockDim.x;
    for (int j = i; j < H * H; j += stride) {
        int k = j >> 9;
        int n = j & (H - 1);
        g_w1T[k][n] = w1[n * H + k];
        g_w2T[k][n] = w2[n * H + k];
    }
}

// ---------------- fused LSTM step (smem-free GEMM + cell update) ----------------
// grid = (H4/64=32, B/64=4) = 128 CTAs, 256 threads.
template <bool DEC>
__global__ void __launch_bounds__(256) k_lstm(const int* __restrict__ xs,
                                              const int* __restrict__ argsort,
                                              int t) {
    const int tid = threadIdx.x;
    const int tx  = tid & 15;             // n quad -> one h (4 gates)
    const int ty  = tid >> 4;             // m quad (4 b's)
    const int n0  = blockIdx.x * 64;
    const int m0  = blockIdx.y * 64;
    const int p   = t & 1;

    const int nw = n0 + 4 * tx;
    const int ma = m0 + 4 * ty;

    ull acc[4][2] = {{0ull, 0ull}, {0ull, 0ull}, {0ull, 0ull}, {0ull, 0ull}};

    if (DEC) {
        gemm_block<H4, B>(&g_dwT[0][nw], &g_ctxT[0][ma], H, acc);
        gemm_block<H4, B>(&g_dwT[H][nw], &g_hT[p][0][ma], H, acc);
    } else {
        gemm_block<H4, B>(&g_ewT[0][nw], &g_hT[p][0][ma], H, acc);
    }

    // ---- epilogue: LSTM cell update for (h = n0/4 + tx, b = ma..ma+3) ----
    const int h_idx = (n0 >> 2) + tx;
    const float* bias4 = DEC ? g_db4 : g_eb4;
    const float* wiv4  = DEC ? g_dwi4 : g_ewi4;
    const float4 bv = *(const float4*)&bias4[nw];
    const float4 wv = *(const float4*)&wiv4[nw];
    const float4 cv = *(const float4*)&g_cT[h_idx][ma];
    const float cin[4] = {cv.x, cv.y, cv.z, cv.w};
    float co[4], ho[4];

#pragma unroll
    for (int r = 0; r < 4; r++) {
        const int b = ma + r;
        const float xb = DEC ? g_dec_in[p][b] : (float)xs[b * L + t];
        const float2 z01 = f2bits(acc[r][0]);
        const float2 z23 = f2bits(acc[r][1]);
        const float zi = z01.x + bv.x + xb * wv.x;
        const float zf = z01.y + bv.y + xb * wv.y;
        const float zg = z23.x + bv.z + xb * wv.z;
        const float zo = z23.y + bv.w + xb * wv.w;
        const float c  = sigmoid_acc(zf) * cin[r] + sigmoid_acc(zi) * tanh_acc(zg);
        const float hn = sigmoid_acc(zo) * tanh_acc(c);
        co[r] = c;
        ho[r] = hn;
    }
    *(float4*)&g_cT[h_idx][ma]        = make_float4(co[0], co[1], co[2], co[3]);
    *(float4*)&g_hT[p ^ 1][h_idx][ma] = make_float4(ho[0], ho[1], ho[2], ho[3]);

    if (!DEC) {
        *(float4*)&g_enc_outT[h_idx][t * B + ma] = make_float4(ho[0], ho[1], ho[2], ho[3]);
#pragma unroll
        for (int r = 0; r < 4; r++) {
            g_enc_outh[((size_t)(ma + r) * L + t) * H + h_idx] = __float2bfloat16_rn(ho[r]);
        }
    }

    if (DEC && blockIdx.x == 0 && tx == 0) {
#pragma unroll
        for (int r = 0; r < 4; r++) {
            const int b = ma + r;
            g_dec_in[p ^ 1][b] = (float)xs[b * L + argsort[b * L + t]];
        }
    }
}

// ---------------- q-proj split-K: qpart[kz] = h @ w2^T over K-chunk ----------------
// grid = (8, 4, 4) = 128 CTAs, KC=128.
__global__ void __launch_bounds__(256) k_qproj(int t) {
    const int tid = threadIdx.x;
    const int tx  = tid & 15;
    const int ty  = tid >> 4;
    const int n0  = blockIdx.x * 64;
    const int m0  = blockIdx.y * 64;
    const int kz  = blockIdx.z;
    const int kbase = kz * 128;
    const int p   = t & 1;

    const int nw = n0 + 4 * tx;
    const int ma = m0 + 4 * ty;

    ull acc[4][2] = {{0ull, 0ull}, {0ull, 0ull}, {0ull, 0ull}, {0ull, 0ull}};
    gemm_block<H, B>(&g_w2T[kbase][nw], &g_hT[p][kbase][ma], 128, acc);

#pragma unroll
    for (int r = 0; r < 4; r++) {
        const float2 z01 = f2bits(acc[r][0]);
        const float2 z23 = f2bits(acc[r][1]);
        *(float4*)&g_qpart[kz][ma + r][nw] = make_float4(z01.x, z01.y, z23.x, z23.y);
    }
}

// ---------------- enc_w1 = enc_out @ w1^T -> bf16  (M = L*B, col m = t*B + b) ----------------
// grid = (8, 512) = 4096 CTAs.
__global__ void __launch_bounds__(256) k_encw1() {
    const int tid = threadIdx.x;
    const int tx  = tid & 15;
    const int ty  = tid >> 4;
    const int n0  = blockIdx.x * 64;
    const int m0  = blockIdx.y * 64;

    const int nw = n0 + 4 * tx;
    const int ma = m0 + 4 * ty;

    ull acc[4][2] = {{0ull, 0ull}, {0ull, 0ull}, {0ull, 0ull}, {0ull, 0ull}};
    gemm_block<H, L * B>(&g_w1T[0][nw], &g_enc_outT[0][ma], H, acc);

#pragma unroll
    for (int r = 0; r < 4; r++) {
        const float2 z01 = f2bits(acc[r][0]);
        const float2 z23 = f2bits(acc[r][1]);
        __nv_bfloat162 p0 = __floats2bfloat162_rn(z01.x, z01.y);
        __nv_bfloat162 p1 = __floats2bfloat162_rn(z23.x, z23.y);
        uint2 pk = make_uint2(*(unsigned*)&p0, *(unsigned*)&p1);
        *(uint2*)&g_enc_w1h[(size_t)(ma + r) * H + nw] = pk;
    }
}

// ---------------- attention: q-reduce + scores + softmax/log_softmax + context ----------------
// One block per batch element b. enc_w1h row index = l*B + b.
__global__ void __launch_bounds__(256) k_attn(const float* __restrict__ vt,
                                              float* __restrict__ out, int t) {
    __shared__ float q_s[H];
    __shared__ float vt_s[H];
    __shared__ float sc[L];
    __shared__ float aj[L];

    const int b = blockIdx.x;
    const int tid = threadIdx.x;
    const int lane = tid & 31;
    const int w = tid >> 5;

    for (int i = tid; i < H; i += 256) {
        float s = 0.0f;
#pragma unroll
        for (int sp = 0; sp < 4; sp++)
            s += g_qpart[sp][b][i];
        q_s[i]  = s;
        vt_s[i] = vt[i];
    }
    __syncthreads();

    // scores[l] = sum_h vt[h] * tanh(enc_w1[b,l,h] + q[h])
#pragma unroll 1
    for (int li = 0; li < 16; li++) {
        const int l = w * 16 + li;
        const uint4* e8 = (const uint4*)(g_enc_w1h + ((size_t)l * B + b) * H);
        float s = 0.f;
#pragma unroll
        for (int j = 0; j < 2; j++) {
            const int base = (lane + j * 32) * 8;
            uint4 u = e8[lane + j * 32];
            float4 q0 = *(const float4*)&q_s[base];
            float4 q1 = *(const float4*)&q_s[base + 4];
            float4 v0 = *(const float4*)&vt_s[base];
            float4 v1 = *(const float4*)&vt_s[base + 4];
            float2 e0 = __bfloat1622float2(*(__nv_bfloat162*)&u.x);
            float2 e1 = __bfloat1622float2(*(__nv_bfloat162*)&u.y);
            float2 e2 = __bfloat1622float2(*(__nv_bfloat162*)&u.z);
            float2 e3 = __bfloat1622float2(*(__nv_bfloat162*)&u.w);
            s += v0.x * tanh_fast(e0.x + q0.x);
            s += v0.y * tanh_fast(e0.y + q0.y);
            s += v0.z * tanh_fast(e1.x + q0.z);
            s += v0.w * tanh_fast(e1.y + q0.w);
            s += v1.x * tanh_fast(e2.x + q1.x);
            s += v1.y * tanh_fast(e2.y + q1.y);
            s += v1.z * tanh_fast(e3.x + q1.z);
            s += v1.w * tanh_fast(e3.y + q1.w);
        }
#pragma unroll
        for (int o = 16; o > 0; o >>= 1) s += __shfl_xor_sync(0xffffffffu, s, o);
        if (lane == 0) sc[l] = s;
    }
    __syncthreads();

    if (w == 0) {
        float sv[4];
        float m = -1e30f;
#pragma unroll
        for (int k = 0; k < 4; k++) { sv[k] = sc[lane * 4 + k]; m = fmaxf(m, sv[k]); }
#pragma unroll
        for (int o = 16; o > 0; o >>= 1) m = fmaxf(m, __shfl_xor_sync(0xffffffffu, m, o));
        float e[4], sum = 0.f;
#pragma unroll
        for (int k = 0; k < 4; k++) { e[k] = __expf(sv[k] - m); sum += e[k]; }
#pragma unroll
        for (int o = 16; o > 0; o >>= 1) sum += __shfl_xor_sync(0xffffffffu, sum, o);
        const float ls  = __logf(sum);
        const float inv = 1.0f / sum;
        float* orow = out + ((size_t)b * L + t) * L;
#pragma unroll
        for (int k = 0; k < 4; k++) {
            orow[lane * 4 + k] = sv[k] - m - ls;
            aj[lane * 4 + k]   = e[k] * inv;
        }
    }
    __syncthreads();

    // context[h] = sum_l aj[l] * enc_out[b,l,h] -> write TRANSPOSED (ctxT[h][b])
    const int h2 = tid * 2;
    float ax = 0.f, ay = 0.f;
    const __nv_bfloat162* base =
        (const __nv_bfloat162*)(g_enc_outh + (size_t)b * L * H + h2);
#pragma unroll 4
    for (int l = 0; l < L; l++) {
        const float a = aj[l];
        float2 v = __bfloat1622float2(base[(size_t)l * (H / 2)]);
        ax += a * v.x;
        ay += a * v.y;
    }
    g_ctxT[h2][b]     = ax;
    g_ctxT[h2 + 1][b] = ay;
}

}  // namespace

extern "C" void kernel_launch(void* const* d_in, const int* in_sizes, int n_in,
                              void* d_out, int out_size) {
    (void)in_sizes; (void)n_in; (void)out_size;
    const int*   xs      = (const int*)d_in[0];
    const int*   argsort = (const int*)d_in[2];
    const float* enc_Wi  = (const float*)d_in[3];
    const float* enc_Wh  = (const float*)d_in[4];
    const float* enc_b   = (const float*)d_in[5];
    const float* dec_Wi  = (const float*)d_in[6];
    const float* dec_Wh  = (const float*)d_in[7];
    const float* dec_b   = (const float*)d_in[8];
    const float* w1      = (const float*)d_in[9];
    const float* w2      = (const float*)d_in[10];
    const float* vt      = (const float*)d_in[11];
    float* out = (float*)d_out;

    k_init<<<128, 256>>>();
    k_repack_enc<<<256, 256>>>(enc_Wh, enc_b, enc_Wi);
    k_repack_dec<<<512, 256>>>(dec_Wi, dec_Wh, dec_b);
    k_repack_w<<<256, 256>>>(w1, w2);

    const dim3 lstm_grid(H4 / 64, B / 64);        // (32, 4) = 128 CTAs
    const dim3 q_grid(H / 64, B / 64, 4);         // (8, 4, 4) = 128 CTAs
    const dim3 encw1_grid(H / 64, (L * B) / 64);  // (8, 512) = 4096 CTAs

    // ---- encoder: 128 fused LSTM steps ----
    for (int t = 0; t < L; t++) {
        k_lstm<false><<<lstm_grid, 256>>>(xs, nullptr, t);
    }

    // ---- hoisted projection enc_w1 = enc_out @ w1^T (bf16 out) ----
    k_encw1<<<encw1_grid, 256>>>();

    // ---- decoder: 128 steps of q-proj -> attention -> fused LSTM ----
    for (int t = 0; t < L; t++) {
        k_qproj<<<q_grid, 256>>>(t);
        k_attn<<<B, 256>>>(vt, out, t);
        k_lstm<true><<<lstm_grid, 256>>>(xs, argsort, t);
    }
}

// round 6
// speedup vs baseline: 1.3205x; 1.3205x over previous
#include <cuda_runtime.h>
#include <cuda_bf16.h>
#include <math.h>

namespace {

constexpr int B  = 256;
constexpr int L  = 128;
constexpr int H  = 512;
constexpr int H4 = 2048;

// ---------------- device state (allocation-free scratch) ----------------
__device__ float g_h[2][B * H];                          // hidden, double buffered by parity
__device__ float g_c[B * H];                             // cell
__device__ float g_enc_out[(size_t)B * L * H];           // fp32 (input to encw1 GEMM)
__device__ __nv_bfloat16 g_enc_outh[(size_t)B * L * H];  // bf16 copy (decode-phase context)
__device__ __nv_bfloat16 g_enc_w1h[(size_t)B * L * H];   // bf16 enc_out @ w1^T (decode scores)
__device__ float g_ctx[B * H];                           // attention context
__device__ float g_dec_in[2][B];                         // decoder scalar input
__device__ float g_ewh4[H4 * H];                         // enc_Wh, gate-interleaved [n'=h*4+g][k]
__device__ float g_eb4[H4];                              // enc bias, interleaved
__device__ float g_ewi4[H4];                             // enc Wi (scalar input), interleaved
__device__ float g_dw4[H4 * 1024];                       // dec [Wi_main | Wh], interleaved, stride 1024
__device__ float g_db4[H4];                              // dec bias, interleaved
__device__ float g_dwi4[H4];                             // dec Wi last column, interleaved
__device__ float g_qpart[8 * B * H];                     // split-K partials for q = h @ w2^T

// ---------------- math helpers ----------------
__device__ __forceinline__ float sigmoid_acc(float x) {
    return 1.0f / (1.0f + __expf(-x));
}
__device__ __forceinline__ float tanh_acc(float x) {
    float e = __expf(-2.0f * fabsf(x));
    float r = (1.0f - e) / (1.0f + e);
    return copysignf(r, x);
}
__device__ __forceinline__ float tanh_fast(float x) {
    float y;
    asm("tanh.approx.f32 %0, %1;" : "=f"(y) : "f"(x));
    return y;
}

// ---------------- init ----------------
__global__ void k_init() {
    int i = blockIdx.x * blockDim.x + threadIdx.x;
    int stride = gridDim.x * blockDim.x;
    for (int j = i; j < B * H; j += stride) {
        g_h[0][j] = 0.0f;
        g_c[j]    = 0.0f;
    }
    if (i < B) g_dec_in[0][i] = 0.0f;
}

// ---------------- one-time repacks: gate-interleave columns (n' = h*4 + g) ----------------
__global__ void k_repack_enc(const float* __restrict__ ewh,
                             const float* __restrict__ eb,
                             const float* __restrict__ ewi) {
    int i = blockIdx.x * blockDim.x + threadIdx.x;
    int stride = gridDim.x * blockDim.x;
    for (int j = i; j < H4 * H; j += stride) {
        int np = j >> 9;
        int k  = j & (H - 1);
        int hh = np >> 2, g = np & 3;
        g_ewh4[j] = ewh[(g * H + hh) * H + k];
    }
    if (i < H4) {
        int hh = i >> 2, g = i & 3;
        g_eb4[i]  = eb[g * H + hh];
        g_ewi4[i] = ewi[g * H + hh];
    }
}

__global__ void k_repack_dec(const float* __restrict__ dwi,
                             const float* __restrict__ dwh,
                             const float* __restrict__ db) {
    int i = blockIdx.x * blockDim.x + threadIdx.x;
    int stride = gridDim.x * blockDim.x;
    for (int j = i; j < H4 * 1024; j += stride) {
        int np = j >> 10;
        int k  = j & 1023;
        int hh = np >> 2, g = np & 3;
        int row = g * H + hh;
        g_dw4[j] = (k < H) ? dwi[row * (H + 1) + k] : dwh[row * H + (k - H)];
    }
    if (i < H4) {
        int hh = i >> 2, g = i & 3;
        g_db4[i]  = db[g * H + hh];
        g_dwi4[i] = dwi[(g * H + hh) * (H + 1) + H];
    }
}

// ---------------- fused LSTM step: GEMM (gate-interleaved) + cell update epilogue ----------------
// Tile 32n x 64m, 256 threads, micro 4n(=4 gates of one h) x 2m. Double-buffered smem.
// grid = (H4/32=64, B/64=4) = 256 CTAs.
template <int KTOT, bool DEC>
__global__ void __launch_bounds__(256) k_lstm(
    const float* __restrict__ W,      // [2048 x KTOT] gate-interleaved rows
    const float* __restrict__ bias4,  // [2048] interleaved
    const float* __restrict__ wiv4,   // [2048] interleaved scalar-input weights
    const int*   __restrict__ xs,
    const int*   __restrict__ argsort,
    int t)
{
    constexpr int NT = KTOT / 16;

    __shared__ float As[2][16][68];   // [k][m], 64 used
    __shared__ float Bs[2][16][36];   // [k][n], 32 used

    const int tid = threadIdx.x;
    const int tx  = tid & 7;             // n quad -> one h, 4 gates
    const int ty  = tid >> 3;            // 0..31 -> 2 m's each
    const int n0  = blockIdx.x * 32;
    const int m0  = blockIdx.y * 64;
    const int p   = t & 1;

    const int brow = tid >> 3;           // 0..31 (W row within tile)
    const int bkq  = (tid & 7) * 2;      // 0..14 (k pair)
    const int am   = tid >> 2;           // 0..63 (A row within tile)
    const int ak   = (tid & 3) * 4;      // 0,4,8,12 (k quad)

    const float* A0 = DEC ? g_ctx : g_h[p];
    const float* A1 = g_h[p];            // dec: h part of concat

    float acc[4][2] = {};                // [gate][r]

    auto gload = [&](int k0, float4& av, float2& wv) {
        wv = *(const float2*)&W[(size_t)(n0 + brow) * KTOT + k0 + bkq];
        const int ka = k0 + ak;
        const float* asrc;
        if (DEC) {
            asrc = (ka < H) ? &A0[(m0 + am) * H + ka]
                            : &A1[(m0 + am) * H + (ka - H)];
        } else {
            asrc = &A0[(m0 + am) * H + ka];
        }
        av = *(const float4*)asrc;
    };
    auto sstore = [&](int buf, float4 av, float2 wv) {
        Bs[buf][bkq + 0][brow] = wv.x;
        Bs[buf][bkq + 1][brow] = wv.y;
        As[buf][ak + 0][am] = av.x;
        As[buf][ak + 1][am] = av.y;
        As[buf][ak + 2][am] = av.z;
        As[buf][ak + 3][am] = av.w;
    };

    {
        float4 av; float2 wv;
        gload(0, av, wv);
        sstore(0, av, wv);
    }
    __syncthreads();

    for (int it = 0; it < NT; it++) {
        float4 av; float2 wv;
        const bool more = (it + 1 < NT);
        if (more) gload((it + 1) * 16, av, wv);

        const int cb = it & 1;
#pragma unroll
        for (int k = 0; k < 16; k++) {
            float4 b4 = *(const float4*)&Bs[cb][k][tx * 4];
            float2 a2 = *(const float2*)&As[cb][k][ty * 2];
            acc[0][0] += a2.x * b4.x;  acc[0][1] += a2.y * b4.x;
            acc[1][0] += a2.x * b4.y;  acc[1][1] += a2.y * b4.y;
            acc[2][0] += a2.x * b4.z;  acc[2][1] += a2.y * b4.z;
            acc[3][0] += a2.x * b4.w;  acc[3][1] += a2.y * b4.w;
        }
        if (more) sstore(cb ^ 1, av, wv);  // writes buffer != cb: no race with readers
        __syncthreads();
    }

    // ---- epilogue: full LSTM cell update for (b = m0+ty*2+r, h = n0/4 + tx) ----
    const int h_idx = (n0 >> 2) + tx;
    const float4 bv = *(const float4*)&bias4[n0 + tx * 4];
    const float4 wv4 = *(const float4*)&wiv4[n0 + tx * 4];

#pragma unroll
    for (int r = 0; r < 2; r++) {
        const int b = m0 + ty * 2 + r;
        const float xb = DEC ? g_dec_in[p][b] : (float)xs[b * L + t];
        const float zi = acc[0][r] + bv.x + xb * wv4.x;
        const float zf = acc[1][r] + bv.y + xb * wv4.y;
        const float zg = acc[2][r] + bv.z + xb * wv4.z;
        const float zo = acc[3][r] + bv.w + xb * wv4.w;
        const int ci = b * H + h_idx;
        const float c  = sigmoid_acc(zf) * g_c[ci] + sigmoid_acc(zi) * tanh_acc(zg);
        const float hn = sigmoid_acc(zo) * tanh_acc(c);
        g_c[ci] = c;
        g_h[p ^ 1][ci] = hn;
        if (!DEC) {
            const size_t eo = ((size_t)b * L + t) * H + h_idx;
            g_enc_out[eo]  = hn;
            g_enc_outh[eo] = __float2bfloat16_rn(hn);
        }
    }

    if (DEC && blockIdx.x == 0 && tx == 0) {
#pragma unroll
        for (int r = 0; r < 2; r++) {
            const int b = m0 + ty * 2 + r;
            g_dec_in[p ^ 1][b] = (float)xs[b * L + argsort[b * L + t]];
        }
    }
}

// ---------------- q-proj split-K GEMM: qpart[kz] = h @ w2^T over K-chunk ----------------
// grid = (8, 4, 8) = 256 CTAs, 256 threads, tile 64x64, micro 4x4. (R3 version, unchanged)
__global__ void __launch_bounds__(256) k_qproj(
    const float* __restrict__ W,    // w2 [512 x 512]
    const float* __restrict__ A,    // h  [256 x 512]
    float* __restrict__ part)       // [8][256][512]
{
    constexpr int KC = 64;
    constexpr int NT = KC / 16;

    __shared__ float As[2][16][68];
    __shared__ float Bs[2][16][68];

    const int tid = threadIdx.x;
    const int tx  = tid & 15;
    const int ty  = tid >> 4;
    const int n0  = blockIdx.x * 64;
    const int m0  = blockIdx.y * 64;
    const int kbase = blockIdx.z * KC;

    const int rl = tid >> 2;
    const int kl = (tid & 3) * 4;

    float acc[4][4] = {};

    auto gload = [&](int k0, float4& av, float4& wv) {
        const int k = k0 + kl;
        av = *(const float4*)&A[(m0 + rl) * H + k];
        wv = *(const float4*)&W[(size_t)(n0 + rl) * H + k];
    };
    auto sstore = [&](int buf, float4 av, float4 wv) {
        As[buf][kl + 0][rl] = av.x; As[buf][kl + 1][rl] = av.y;
        As[buf][kl + 2][rl] = av.z; As[buf][kl + 3][rl] = av.w;
        Bs[buf][kl + 0][rl] = wv.x; Bs[buf][kl + 1][rl] = wv.y;
        Bs[buf][kl + 2][rl] = wv.z; Bs[buf][kl + 3][rl] = wv.w;
    };

    {
        float4 av, wv;
        gload(kbase, av, wv);
        sstore(0, av, wv);
    }
    __syncthreads();

    for (int it = 0; it < NT; it++) {
        float4 av, wv;
        const bool more = (it + 1 < NT);
        if (more) gload(kbase + (it + 1) * 16, av, wv);
        const int cb = it & 1;
#pragma unroll
        for (int k = 0; k < 16; k++) {
            float4 a = *(const float4*)&As[cb][k][ty * 4];
            float4 b = *(const float4*)&Bs[cb][k][tx * 4];
            acc[0][0] += a.x * b.x; acc[0][1] += a.x * b.y; acc[0][2] += a.x * b.z; acc[0][3] += a.x * b.w;
            acc[1][0] += a.y * b.x; acc[1][1] += a.y * b.y; acc[1][2] += a.y * b.z; acc[1][3] += a.y * b.w;
            acc[2][0] += a.z * b.x; acc[2][1] += a.z * b.y; acc[2][2] += a.z * b.z; acc[2][3] += a.z * b.w;
            acc[3][0] += a.w * b.x; acc[3][1] += a.w * b.y; acc[3][2] += a.w * b.z; acc[3][3] += a.w * b.w;
        }
        if (more) sstore(cb ^ 1, av, wv);
        __syncthreads();
    }

    float* dst = part + (size_t)blockIdx.z * (B * H);
#pragma unroll
    for (int i = 0; i < 4; i++) {
        float4 o = make_float4(acc[i][0], acc[i][1], acc[i][2], acc[i][3]);
        *(float4*)&dst[(size_t)(m0 + ty * 4 + i) * H + n0 + tx * 4] = o;
    }
}

// ---------------- enc_w1 = enc_out @ w1^T -> bf16  (M=32768, N=512, K=512) ----------------
// (R3 version, unchanged) grid = (8, 512).
__global__ void __launch_bounds__(256) k_encw1(const float* __restrict__ w1) {
    __shared__ float As[16][68];
    __shared__ float Bs[16][68];

    const int tid = threadIdx.x;
    const int tx = tid & 15;
    const int ty = tid >> 4;
    const int n0 = blockIdx.x * 64;
    const int m0 = blockIdx.y * 64;

    const int rl = tid >> 2;
    const int kl = (tid & 3) * 4;

    float acc[4][4] = {};

    for (int k0 = 0; k0 < H; k0 += 16) {
        __syncthreads();
        {
            float4 av = *(const float4*)&g_enc_out[(size_t)(m0 + rl) * H + k0 + kl];
            As[kl + 0][rl] = av.x; As[kl + 1][rl] = av.y;
            As[kl + 2][rl] = av.z; As[kl + 3][rl] = av.w;
            float4 bv = *(const float4*)&w1[(n0 + rl) * H + k0 + kl];
            Bs[kl + 0][rl] = bv.x; Bs[kl + 1][rl] = bv.y;
            Bs[kl + 2][rl] = bv.z; Bs[kl + 3][rl] = bv.w;
        }
        __syncthreads();
#pragma unroll
        for (int k = 0; k < 16; k++) {
            float4 a = *(const float4*)&As[k][ty * 4];
            float4 w = *(const float4*)&Bs[k][tx * 4];
            acc[0][0] += a.x * w.x; acc[0][1] += a.x * w.y; acc[0][2] += a.x * w.z; acc[0][3] += a.x * w.w;
            acc[1][0] += a.y * w.x; acc[1][1] += a.y * w.y; acc[1][2] += a.y * w.z; acc[1][3] += a.y * w.w;
            acc[2][0] += a.z * w.x; acc[2][1] += a.z * w.y; acc[2][2] += a.z * w.z; acc[2][3] += a.z * w.w;
            acc[3][0] += a.w * w.x; acc[3][1] += a.w * w.y; acc[3][2] += a.w * w.z; acc[3][3] += a.w * w.w;
        }
    }
#pragma unroll
    for (int i = 0; i < 4; i++) {
        __nv_bfloat162 p0 = __floats2bfloat162_rn(acc[i][0], acc[i][1]);
        __nv_bfloat162 p1 = __floats2bfloat162_rn(acc[i][2], acc[i][3]);
        uint2 pk = make_uint2(*(unsigned*)&p0, *(unsigned*)&p1);
        *(uint2*)&g_enc_w1h[(size_t)(m0 + ty * 4 + i) * H + n0 + tx * 4] = pk;
    }
}

// ---------------- attention: q-reduce + scores + softmax/log_softmax + context ----------------
// (R3 version, unchanged)
__global__ void __launch_bounds__(256) k_attn(const float* __restrict__ vt,
                                              float* __restrict__ out, int t) {
    __shared__ float q_s[H];
    __shared__ float vt_s[H];
    __shared__ float sc[L];
    __shared__ float aj[L];

    const int b = blockIdx.x;
    const int tid = threadIdx.x;
    const int lane = tid & 31;
    const int w = tid >> 5;

    for (int i = tid; i < H; i += 256) {
        float s = 0.0f;
#pragma unroll
        for (int sp = 0; sp < 8; sp++)
            s += g_qpart[(size_t)sp * (B * H) + b * H + i];
        q_s[i]  = s;
        vt_s[i] = vt[i];
    }
    __syncthreads();

#pragma unroll 1
    for (int li = 0; li < 16; li++) {
        const int l = w * 16 + li;
        const uint4* e8 = (const uint4*)(g_enc_w1h + (size_t)(b * L + l) * H);
        float s = 0.f;
#pragma unroll
        for (int j = 0; j < 2; j++) {
            const int base = (lane + j * 32) * 8;
            uint4 u = e8[lane + j * 32];
            float4 q0 = *(const float4*)&q_s[base];
            float4 q1 = *(const float4*)&q_s[base + 4];
            float4 v0 = *(const float4*)&vt_s[base];
            float4 v1 = *(const float4*)&vt_s[base + 4];
            float2 e0 = __bfloat1622float2(*(__nv_bfloat162*)&u.x);
            float2 e1 = __bfloat1622float2(*(__nv_bfloat162*)&u.y);
            float2 e2 = __bfloat1622float2(*(__nv_bfloat162*)&u.z);
            float2 e3 = __bfloat1622float2(*(__nv_bfloat162*)&u.w);
            s += v0.x * tanh_fast(e0.x + q0.x);
            s += v0.y * tanh_fast(e0.y + q0.y);
            s += v0.z * tanh_fast(e1.x + q0.z);
            s += v0.w * tanh_fast(e1.y + q0.w);
            s += v1.x * tanh_fast(e2.x + q1.x);
            s += v1.y * tanh_fast(e2.y + q1.y);
            s += v1.z * tanh_fast(e3.x + q1.z);
            s += v1.w * tanh_fast(e3.y + q1.w);
        }
#pragma unroll
        for (int o = 16; o > 0; o >>= 1) s += __shfl_xor_sync(0xffffffffu, s, o);
        if (lane == 0) sc[l] = s;
    }
    __syncthreads();

    if (w == 0) {
        float sv[4];
        float m = -1e30f;
#pragma unroll
        for (int k = 0; k < 4; k++) { sv[k] = sc[lane * 4 + k]; m = fmaxf(m, sv[k]); }
#pragma unroll
        for (int o = 16; o > 0; o >>= 1) m = fmaxf(m, __shfl_xor_sync(0xffffffffu, m, o));
        float e[4], sum = 0.f;
#pragma unroll
        for (int k = 0; k < 4; k++) { e[k] = __expf(sv[k] - m); sum += e[k]; }
#pragma unroll
        for (int o = 16; o > 0; o >>= 1) sum += __shfl_xor_sync(0xffffffffu, sum, o);
        const float ls  = __logf(sum);
        const float inv = 1.0f / sum;
        float* orow = out + ((size_t)b * L + t) * L;
#pragma unroll
        for (int k = 0; k < 4; k++) {
            orow[lane * 4 + k] = sv[k] - m - ls;
            aj[lane * 4 + k]   = e[k] * inv;
        }
    }
    __syncthreads();

    const int h2 = tid * 2;
    float ax = 0.f, ay = 0.f;
    const __nv_bfloat162* base =
        (const __nv_bfloat162*)(g_enc_outh + (size_t)b * L * H + h2);
#pragma unroll 4
    for (int l = 0; l < L; l++) {
        const float a = aj[l];
        float2 v = __bfloat1622float2(base[(size_t)l * (H / 2)]);
        ax += a * v.x;
        ay += a * v.y;
    }
    g_ctx[b * H + h2]     = ax;
    g_ctx[b * H + h2 + 1] = ay;
}

}  // namespace

extern "C" void kernel_launch(void* const* d_in, const int* in_sizes, int n_in,
                              void* d_out, int out_size) {
    (void)in_sizes; (void)n_in; (void)out_size;
    const int*   xs      = (const int*)d_in[0];
    const int*   argsort = (const int*)d_in[2];
    const float* enc_Wi  = (const float*)d_in[3];
    const float* enc_Wh  = (const float*)d_in[4];
    const float* enc_b   = (const float*)d_in[5];
    const float* dec_Wi  = (const float*)d_in[6];
    const float* dec_Wh  = (const float*)d_in[7];
    const float* dec_b   = (const float*)d_in[8];
    const float* w1      = (const float*)d_in[9];
    const float* w2      = (const float*)d_in[10];
    const float* vt      = (const float*)d_in[11];
    float* out = (float*)d_out;

    float *p_h, *p_ewh4, *p_eb4, *p_ewi4, *p_dw4, *p_db4, *p_dwi4, *p_qpart;
    cudaGetSymbolAddress((void**)&p_h,     g_h);
    cudaGetSymbolAddress((void**)&p_ewh4,  g_ewh4);
    cudaGetSymbolAddress((void**)&p_eb4,   g_eb4);
    cudaGetSymbolAddress((void**)&p_ewi4,  g_ewi4);
    cudaGetSymbolAddress((void**)&p_dw4,   g_dw4);
    cudaGetSymbolAddress((void**)&p_db4,   g_db4);
    cudaGetSymbolAddress((void**)&p_dwi4,  g_dwi4);
    cudaGetSymbolAddress((void**)&p_qpart, g_qpart);

    k_init<<<128, 256>>>();
    k_repack_enc<<<256, 256>>>(enc_Wh, enc_b, enc_Wi);
    k_repack_dec<<<512, 256>>>(dec_Wi, dec_Wh, dec_b);

    const dim3 lstm_grid(H4 / 32, B / 64);          // (64, 4) = 256 CTAs
    const dim3 q_grid(H / 64, B / 64, 8);           // (8, 4, 8) = 256 CTAs
    const dim3 encw1_grid(H / 64, (B * L) / 64);    // (8, 512) = 4096 CTAs

    // ---- encoder: 128 fused LSTM steps ----
    for (int t = 0; t < L; t++) {
        k_lstm<512, false><<<lstm_grid, 256>>>(p_ewh4, p_eb4, p_ewi4, xs, nullptr, t);
    }

    // ---- hoisted projection enc_w1 = enc_out @ w1^T (bf16 out) ----
    k_encw1<<<encw1_grid, 256>>>(w1);

    // ---- decoder: 128 steps of q-proj -> attention -> fused LSTM ----
    for (int t = 0; t < L; t++) {
        const float* hp = p_h + (size_t)(t & 1) * (B * H);
        k_qproj<<<q_grid, 256>>>(w2, hp, p_qpart);
        k_attn<<<B, 256>>>(vt, out, t);
        k_lstm<1024, true><<<lstm_grid, 256>>>(p_dw4, p_db4, p_dwi4, xs, argsort, t);
    }
}